// round 16
// baseline (speedup 1.0000x reference)
#include <cuda_runtime.h>
#include <cuda_fp16.h>

// RoIMaskAlign via NHWC-fp16 staging, round 16: R15 with the staging-store
// alignment fixed (SSTR=258 + float2 STS, 8B-aligned for every bin).
// features (B=2, C=256, H=200, W=272) fp32, rois (K, 5) fp32
// out (K, C, 14, 14) fp32

#define PH 14
#define PW 14

static constexpr int   Bc = 2;
static constexpr int   Cc = 256;
static constexpr int   Hc = 200;
static constexpr int   Wc = 272;
static constexpr float SCALE     = 0.25f;
static constexpr float ROI_SCALE = 1.2f;

// NHWC fp16 scratch: (B, H, W, C) = 2*200*272*256 halves = 55.7 MB
__device__ __align__(16) __half g_nhwc[(size_t)Bc * Hc * Wc * Cc];

// packed f32x2 add (SASS FFMA2-class; only reachable via PTX)
__device__ __forceinline__ void add_f32x2(float2& acc, float lo, float hi)
{
    unsigned long long a, b;
    asm("mov.b64 %0, {%1, %2};" : "=l"(a) : "f"(acc.x), "f"(acc.y));
    asm("mov.b64 %0, {%1, %2};" : "=l"(b) : "f"(lo), "f"(hi));
    unsigned long long c;
    asm("add.rn.f32x2 %0, %1, %2;" : "=l"(c) : "l"(a), "l"(b));
    asm("mov.b64 {%0, %1}, %2;" : "=f"(acc.x), "=f"(acc.y) : "l"(c));
}

// ---------------------------------------------------------------------------
// Kernel 1: NCHW fp32 -> NHWC fp16 transpose (R12 version, DRAM-pinned).
// ---------------------------------------------------------------------------
__global__ __launch_bounds__(256)
void transpose_kernel(const float* __restrict__ feat)
{
    __shared__ __align__(16) __half s[16][264];

    int x0 = blockIdx.x * 16;
    int y  = blockIdx.y;
    int b  = blockIdx.z;
    int tid = threadIdx.x;
    int xl = tid & 15;
    int ci = tid >> 4;

    const float* fp = feat + (((size_t)b * Cc) * Hc + y) * Wc + x0 + xl;
    #pragma unroll
    for (int k = 0; k < 16; k++) {
        int c = k * 16 + ci;
        s[xl][c] = __float2half_rn(__ldcs(fp + (size_t)c * (Hc * Wc)));
    }
    __syncthreads();

    __half* op = g_nhwc + (((size_t)b * Hc + y) * Wc + x0) * Cc;
    #pragma unroll
    for (int j = 0; j < 2; j++) {
        int u = tid + j * 256;
        int x = u >> 5;
        int k = u & 31;
        *reinterpret_cast<uint4*>(op + (size_t)x * Cc + k * 8) =
            *reinterpret_cast<const uint4*>(&s[x][k * 8]);
    }
}

// ---------------------------------------------------------------------------
// Kernel 2: gather (R14 structure). Block = (n, php); 14 warps. Warp w:
// ph_local = w/7, pw = (w%7)*2 + {0,1}. Lane owns 8 channels. HFMA2 taps,
// per-tap wt!=0 guard, 32-bit byte offsets, f32x2 flush. Staging rows at
// stride 258 (2-way epilogue conflicts), stores as STS.64 (alignment-safe).
// ---------------------------------------------------------------------------
static constexpr int BINS = 28;
static constexpr int SSTR = 258;    // mod 32 == 2 -> 2-way column conflicts

__global__ __launch_bounds__(448, 2)
void gather_kernel(const float* __restrict__ rois,
                   float* __restrict__ out)
{
    __shared__ __align__(16) float s[BINS * SSTR];   // 28*258*4 = 28896 B

    int n   = blockIdx.x;
    int php = blockIdx.y;            // 0..6
    int wid  = threadIdx.x >> 5;     // 0..13
    int lane = threadIdx.x & 31;
    int ph_l   = wid / 7;            // 0..1
    int pwpair = wid % 7;            // 0..6
    int ph  = php * 2 + ph_l;

    const float* r = rois + n * 5;
    int   b  = (int)r[0];
    float rx1 = r[1], ry1 = r[2], rx2 = r[3], ry2 = r[4];

    float cx = (rx1 + rx2) * 0.5f;
    float cy = (ry1 + ry2) * 0.5f;
    float rw = (rx2 - rx1) * ROI_SCALE;
    float rh = (ry2 - ry1) * ROI_SCALE;
    float x1s = (cx - 0.5f * rw) * SCALE;
    float x2s = (cx + 0.5f * rw) * SCALE;
    float y1s = (cy - 0.5f * rh) * SCALE;
    float y2s = (cy + 0.5f * rh) * SCALE;

    float roi_w = fmaxf(x2s - x1s, 1.0f);
    float roi_h = fmaxf(y2s - y1s, 1.0f);
    float bin_w = roi_w * (1.0f / PW);
    float bin_h = roi_h * (1.0f / PH);

    // base pointer with lane offset folded in; 32-bit byte offsets.
    const char* tbl = reinterpret_cast<const char*>(g_nhwc) + lane * 16;

    #pragma unroll
    for (int i = 0; i < 2; i++) {
        int pw  = pwpair * 2 + i;
        int bin = ph_l * PW + pw;

        float2 A0 = make_float2(0.f, 0.f);   // channels 0,1
        float2 A1 = make_float2(0.f, 0.f);   // channels 2,3
        float2 A2 = make_float2(0.f, 0.f);   // channels 4,5
        float2 A3 = make_float2(0.f, 0.f);   // channels 6,7

        unsigned xo0[2], xo1[2];
        float lx[2], hx[2];
        bool  vx[2];
        #pragma unroll
        for (int sx = 0; sx < 2; sx++) {
            float x = x1s + ((float)pw + ((float)sx + 0.5f) * 0.5f) * bin_w;
            vx[sx] = (x > -1.0f) && (x < (float)Wc);
            float xc = fminf(fmaxf(x, 0.0f), (float)(Wc - 1));
            int x0 = (int)floorf(xc);
            xo0[sx] = (unsigned)x0 << 9;
            xo1[sx] = (unsigned)min(x0 + 1, Wc - 1) << 9;
            lx[sx] = xc - (float)x0;
            hx[sx] = 1.0f - lx[sx];
        }

        #define TAP(off, wt) do {                                               \
            if ((wt) != 0.0f) {                                                 \
                uint4 v = *reinterpret_cast<const uint4*>(tbl + (off));         \
                const __half2* hp = reinterpret_cast<const __half2*>(&v);       \
                __half2 wh = __float2half2_rn(wt);                              \
                h0 = __hfma2(wh, hp[0], h0);                                    \
                h1 = __hfma2(wh, hp[1], h1);                                    \
                h2 = __hfma2(wh, hp[2], h2);                                    \
                h3 = __hfma2(wh, hp[3], h3);                                    \
            }                                                                   \
        } while (0)

        #pragma unroll
        for (int sy = 0; sy < 2; sy++) {
            float y = y1s + ((float)ph + (sy ? 0.75f : 0.25f)) * bin_h;
            bool vy = (y > -1.0f) && (y < (float)Hc);
            float yc = fminf(fmaxf(y, 0.0f), (float)(Hc - 1));
            int y0 = (int)floorf(yc);
            int y1b = min(y0 + 1, Hc - 1);
            float ly = yc - (float)y0;
            float hy = 1.0f - ly;

            unsigned rb0 = (unsigned)((b * Hc + y0)  * Wc) << 9;
            unsigned rb1 = (unsigned)((b * Hc + y1b) * Wc) << 9;

            __half2 h0 = __float2half2_rn(0.f);
            __half2 h1 = h0, h2 = h0, h3 = h0;

            #pragma unroll
            for (int sx = 0; sx < 2; sx++) {
                float wq = (vy && vx[sx]) ? 0.25f : 0.0f;   // validity + mean
                float w00 = wq * hy * hx[sx];
                float w01 = wq * hy * lx[sx];
                float w10 = wq * ly * hx[sx];
                float w11 = wq * ly * lx[sx];
                TAP(rb0 + xo0[sx], w00);
                TAP(rb0 + xo1[sx], w01);
                TAP(rb1 + xo0[sx], w10);
                TAP(rb1 + xo1[sx], w11);
            }

            // per-sy fp32 flush, packed f32x2 adds
            float2 f0 = __half22float2(h0);
            float2 f1 = __half22float2(h1);
            float2 f2 = __half22float2(h2);
            float2 f3 = __half22float2(h3);
            add_f32x2(A0, f0.x, f0.y);
            add_f32x2(A1, f1.x, f1.y);
            add_f32x2(A2, f2.x, f2.y);
            add_f32x2(A3, f3.x, f3.y);
        }
        #undef TAP

        // staging stores: STS.64 only (byte offset bin*1032 + lane*32 is
        // always 8B-aligned; 16B alignment NOT guaranteed for odd bins)
        float* dst = s + bin * SSTR + lane * 8;
        *reinterpret_cast<float2*>(dst)     = A0;
        *reinterpret_cast<float2*>(dst + 2) = A1;
        *reinterpret_cast<float2*>(dst + 4) = A2;
        *reinterpret_cast<float2*>(dst + 6) = A3;
    }

    __syncthreads();

    // epilogue: LDS.64 channel pairs (offset (lane*258 + c)*4, c even -> 8B
    // aligned; stride 258 -> 2-way conflicts), coalesced 28-float runs.
    for (int c = 2 * wid; c < Cc; c += 28) {
        if (lane < BINS) {
            float2 v = *reinterpret_cast<const float2*>(&s[lane * SSTR + c]);
            size_t o = ((size_t)n * Cc + c) * (PH * PW) + php * BINS + lane;
            __stcs(out + o, v.x);
            __stcs(out + o + (PH * PW), v.y);
        }
    }
}

extern "C" void kernel_launch(void* const* d_in, const int* in_sizes, int n_in,
                              void* d_out, int out_size)
{
    const float* feat = (const float*)d_in[0];
    const float* rois = (const float*)d_in[1];
    float* out = (float*)d_out;

    int K = in_sizes[1] / 5;

    dim3 tg(Wc / 16, Hc, Bc);          // 17 x 200 x 2
    transpose_kernel<<<tg, 256>>>(feat);

    dim3 gg(K, PH / 2);                // K x 7
    gather_kernel<<<gg, 448>>>(rois, out);
}

// round 17
// speedup vs baseline: 1.0548x; 1.0548x over previous
#include <cuda_runtime.h>
#include <cuda_fp16.h>

// RoIMaskAlign via NHWC-fp16 staging, round 17: R16 + branch-free batched
// tap loads (8 unguarded LDG.128 per sy-group -> real MLP=8 at 72-reg budget).
// features (B=2, C=256, H=200, W=272) fp32, rois (K, 5) fp32
// out (K, C, 14, 14) fp32

#define PH 14
#define PW 14

static constexpr int   Bc = 2;
static constexpr int   Cc = 256;
static constexpr int   Hc = 200;
static constexpr int   Wc = 272;
static constexpr float SCALE     = 0.25f;
static constexpr float ROI_SCALE = 1.2f;

// NHWC fp16 scratch: (B, H, W, C) = 2*200*272*256 halves = 55.7 MB
__device__ __align__(16) __half g_nhwc[(size_t)Bc * Hc * Wc * Cc];

// packed f32x2 add (SASS FFMA2-class; only reachable via PTX)
__device__ __forceinline__ void add_f32x2(float2& acc, float lo, float hi)
{
    unsigned long long a, b;
    asm("mov.b64 %0, {%1, %2};" : "=l"(a) : "f"(acc.x), "f"(acc.y));
    asm("mov.b64 %0, {%1, %2};" : "=l"(b) : "f"(lo), "f"(hi));
    unsigned long long c;
    asm("add.rn.f32x2 %0, %1, %2;" : "=l"(c) : "l"(a), "l"(b));
    asm("mov.b64 {%0, %1}, %2;" : "=f"(acc.x), "=f"(acc.y) : "l"(c));
}

// ---------------------------------------------------------------------------
// Kernel 1: NCHW fp32 -> NHWC fp16 transpose (R12 version, DRAM-pinned).
// ---------------------------------------------------------------------------
__global__ __launch_bounds__(256)
void transpose_kernel(const float* __restrict__ feat)
{
    __shared__ __align__(16) __half s[16][264];

    int x0 = blockIdx.x * 16;
    int y  = blockIdx.y;
    int b  = blockIdx.z;
    int tid = threadIdx.x;
    int xl = tid & 15;
    int ci = tid >> 4;

    const float* fp = feat + (((size_t)b * Cc) * Hc + y) * Wc + x0 + xl;
    #pragma unroll
    for (int k = 0; k < 16; k++) {
        int c = k * 16 + ci;
        s[xl][c] = __float2half_rn(__ldcs(fp + (size_t)c * (Hc * Wc)));
    }
    __syncthreads();

    __half* op = g_nhwc + (((size_t)b * Hc + y) * Wc + x0) * Cc;
    #pragma unroll
    for (int j = 0; j < 2; j++) {
        int u = tid + j * 256;
        int x = u >> 5;
        int k = u & 31;
        *reinterpret_cast<uint4*>(op + (size_t)x * Cc + k * 8) =
            *reinterpret_cast<const uint4*>(&s[x][k * 8]);
    }
}

// ---------------------------------------------------------------------------
// Kernel 2: gather. Block = (n, php); 14 warps. Warp w: ph_local = w/7,
// pw = (w%7)*2 + {0,1}. Lane owns 8 channels. Per sy-group: 8 weights
// computed, then 8 UNGUARDED uint4 loads back-to-back (true MLP=8), then
// HFMA2 consume. Validity folds into the weights (0-weight taps load but
// contribute nothing; addresses always clamped in-bounds).
// ---------------------------------------------------------------------------
static constexpr int BINS = 28;
static constexpr int SSTR = 258;    // mod 32 == 2 -> 2-way epilogue conflicts

__global__ __launch_bounds__(448, 2)
void gather_kernel(const float* __restrict__ rois,
                   float* __restrict__ out)
{
    __shared__ __align__(16) float s[BINS * SSTR];   // 28896 B

    int n   = blockIdx.x;
    int php = blockIdx.y;            // 0..6
    int wid  = threadIdx.x >> 5;     // 0..13
    int lane = threadIdx.x & 31;
    int ph_l   = wid / 7;            // 0..1
    int pwpair = wid % 7;            // 0..6
    int ph  = php * 2 + ph_l;

    const float* r = rois + n * 5;
    int   b  = (int)r[0];
    float rx1 = r[1], ry1 = r[2], rx2 = r[3], ry2 = r[4];

    float cx = (rx1 + rx2) * 0.5f;
    float cy = (ry1 + ry2) * 0.5f;
    float rw = (rx2 - rx1) * ROI_SCALE;
    float rh = (ry2 - ry1) * ROI_SCALE;
    float x1s = (cx - 0.5f * rw) * SCALE;
    float x2s = (cx + 0.5f * rw) * SCALE;
    float y1s = (cy - 0.5f * rh) * SCALE;
    float y2s = (cy + 0.5f * rh) * SCALE;

    float roi_w = fmaxf(x2s - x1s, 1.0f);
    float roi_h = fmaxf(y2s - y1s, 1.0f);
    float bin_w = roi_w * (1.0f / PW);
    float bin_h = roi_h * (1.0f / PH);

    // base pointer with lane offset folded in; 32-bit byte offsets.
    const char* tbl = reinterpret_cast<const char*>(g_nhwc) + lane * 16;

    #pragma unroll
    for (int i = 0; i < 2; i++) {
        int pw  = pwpair * 2 + i;
        int bin = ph_l * PW + pw;

        float2 A0 = make_float2(0.f, 0.f);
        float2 A1 = make_float2(0.f, 0.f);
        float2 A2 = make_float2(0.f, 0.f);
        float2 A3 = make_float2(0.f, 0.f);

        unsigned xo0[2], xo1[2];
        float lx[2], hx[2];
        float mx[2];                 // 0.25 if x-valid else 0
        #pragma unroll
        for (int sx = 0; sx < 2; sx++) {
            float x = x1s + ((float)pw + ((float)sx + 0.5f) * 0.5f) * bin_w;
            mx[sx] = ((x > -1.0f) && (x < (float)Wc)) ? 0.25f : 0.0f;
            float xc = fminf(fmaxf(x, 0.0f), (float)(Wc - 1));
            int x0 = (int)floorf(xc);
            xo0[sx] = (unsigned)x0 << 9;
            xo1[sx] = (unsigned)min(x0 + 1, Wc - 1) << 9;
            lx[sx] = xc - (float)x0;
            hx[sx] = 1.0f - lx[sx];
        }

        #pragma unroll
        for (int sy = 0; sy < 2; sy++) {
            float y = y1s + ((float)ph + (sy ? 0.75f : 0.25f)) * bin_h;
            float vyf = ((y > -1.0f) && (y < (float)Hc)) ? 1.0f : 0.0f;
            float yc = fminf(fmaxf(y, 0.0f), (float)(Hc - 1));
            int y0 = (int)floorf(yc);
            int y1b = min(y0 + 1, Hc - 1);
            float ly = yc - (float)y0;
            float hy = 1.0f - ly;

            unsigned rb0 = (unsigned)((b * Hc + y0)  * Wc) << 9;
            unsigned rb1 = (unsigned)((b * Hc + y1b) * Wc) << 9;

            float m0 = vyf * mx[0];
            float m1 = vyf * mx[1];

            // 8 weights + 8 offsets, then 8 unguarded loads back-to-back
            float wt[8];
            wt[0] = m0 * hy * hx[0];  wt[1] = m0 * hy * lx[0];
            wt[2] = m0 * ly * hx[0];  wt[3] = m0 * ly * lx[0];
            wt[4] = m1 * hy * hx[1];  wt[5] = m1 * hy * lx[1];
            wt[6] = m1 * ly * hx[1];  wt[7] = m1 * ly * lx[1];

            unsigned off[8];
            off[0] = rb0 + xo0[0];  off[1] = rb0 + xo1[0];
            off[2] = rb1 + xo0[0];  off[3] = rb1 + xo1[0];
            off[4] = rb0 + xo0[1];  off[5] = rb0 + xo1[1];
            off[6] = rb1 + xo0[1];  off[7] = rb1 + xo1[1];

            uint4 v[8];
            #pragma unroll
            for (int t = 0; t < 8; t++)
                v[t] = *reinterpret_cast<const uint4*>(tbl + off[t]);

            __half2 h0 = __float2half2_rn(0.f);
            __half2 h1 = h0, h2 = h0, h3 = h0;
            #pragma unroll
            for (int t = 0; t < 8; t++) {
                const __half2* hp = reinterpret_cast<const __half2*>(&v[t]);
                __half2 wh = __float2half2_rn(wt[t]);
                h0 = __hfma2(wh, hp[0], h0);
                h1 = __hfma2(wh, hp[1], h1);
                h2 = __hfma2(wh, hp[2], h2);
                h3 = __hfma2(wh, hp[3], h3);
            }

            float2 f0 = __half22float2(h0);
            float2 f1 = __half22float2(h1);
            float2 f2 = __half22float2(h2);
            float2 f3 = __half22float2(h3);
            add_f32x2(A0, f0.x, f0.y);
            add_f32x2(A1, f1.x, f1.y);
            add_f32x2(A2, f2.x, f2.y);
            add_f32x2(A3, f3.x, f3.y);
        }

        // staging stores: STS.64 (8B-aligned for every bin)
        float* dst = s + bin * SSTR + lane * 8;
        *reinterpret_cast<float2*>(dst)     = A0;
        *reinterpret_cast<float2*>(dst + 2) = A1;
        *reinterpret_cast<float2*>(dst + 4) = A2;
        *reinterpret_cast<float2*>(dst + 6) = A3;
    }

    __syncthreads();

    // epilogue: LDS.64 channel pairs (stride 258 -> 2-way conflicts),
    // coalesced 28-float output runs.
    for (int c = 2 * wid; c < Cc; c += 28) {
        if (lane < BINS) {
            float2 v = *reinterpret_cast<const float2*>(&s[lane * SSTR + c]);
            size_t o = ((size_t)n * Cc + c) * (PH * PW) + php * BINS + lane;
            __stcs(out + o, v.x);
            __stcs(out + o + (PH * PW), v.y);
        }
    }
}

extern "C" void kernel_launch(void* const* d_in, const int* in_sizes, int n_in,
                              void* d_out, int out_size)
{
    const float* feat = (const float*)d_in[0];
    const float* rois = (const float*)d_in[1];
    float* out = (float*)d_out;

    int K = in_sizes[1] / 5;

    dim3 tg(Wc / 16, Hc, Bc);          // 17 x 200 x 2
    transpose_kernel<<<tg, 256>>>(feat);

    dim3 gg(K, PH / 2);                // K x 7
    gather_kernel<<<gg, 448>>>(rois, out);
}